// round 2
// baseline (speedup 1.0000x reference)
#include <cuda_runtime.h>

// Problem constants
#define NTOK 4096   // B*T
#define Dm   256
#define Ee   4
#define Cc   4
#define DCc  64
#define Hh   2
#define DHh  32
#define Tt   1024
#define NGRP 128    // B*C*E*H

// Scratch (device globals; no runtime allocation allowed)
__device__ __align__(16) float g_xn[NTOK * Dm];
__device__ __align__(16) float g_gate[NTOK * Ee];
__device__ __align__(16) float g_q[NGRP * Tt * DHh];
__device__ __align__(16) float g_k[NGRP * Tt * DHh];
__device__ __align__(16) float g_v[NGRP * Tt * DHh];
__device__ __align__(16) float g_y[(NGRP / Hh) * Tt * DCc]; // [B,C,E,T,DC]
__device__ __align__(16) float g_z[NTOK * Dm];

// ---------------------------------------------------------------------------
// Kernel 1: LayerNorm + router softmax gate. 1 block per token, 256 threads.
// ---------------------------------------------------------------------------
__global__ void k_ln_router(const float* __restrict__ x,
                            const float* __restrict__ nw,
                            const float* __restrict__ rw,
                            const float* __restrict__ rb) {
    int tok  = blockIdx.x;
    int tid  = threadIdx.x;
    int lane = tid & 31, wid = tid >> 5;

    float v  = x[tok * Dm + tid];
    float s1 = v, s2 = v * v;
#pragma unroll
    for (int o = 16; o; o >>= 1) {
        s1 += __shfl_xor_sync(0xffffffffu, s1, o);
        s2 += __shfl_xor_sync(0xffffffffu, s2, o);
    }
    __shared__ float sh1[8], sh2[8];
    if (lane == 0) { sh1[wid] = s1; sh2[wid] = s2; }
    __syncthreads();
    float a1 = 0.f, a2 = 0.f;
#pragma unroll
    for (int w = 0; w < 8; w++) { a1 += sh1[w]; a2 += sh2[w]; }
    float mean = a1 * (1.f / Dm);
    float var  = a2 * (1.f / Dm) - mean * mean;
    float xnv  = (v - mean) * rsqrtf(var + 1e-5f) * nw[tid];
    g_xn[tok * Dm + tid] = xnv;

    // router logits
    float r0 = xnv * rw[0 * Dm + tid];
    float r1 = xnv * rw[1 * Dm + tid];
    float r2 = xnv * rw[2 * Dm + tid];
    float r3 = xnv * rw[3 * Dm + tid];
#pragma unroll
    for (int o = 16; o; o >>= 1) {
        r0 += __shfl_xor_sync(0xffffffffu, r0, o);
        r1 += __shfl_xor_sync(0xffffffffu, r1, o);
        r2 += __shfl_xor_sync(0xffffffffu, r2, o);
        r3 += __shfl_xor_sync(0xffffffffu, r3, o);
    }
    __shared__ float sr[4][8];
    if (lane == 0) { sr[0][wid] = r0; sr[1][wid] = r1; sr[2][wid] = r2; sr[3][wid] = r3; }
    __syncthreads();
    if (tid == 0) {
        float lg[4];
#pragma unroll
        for (int e = 0; e < 4; e++) {
            float s = rb[e];
#pragma unroll
            for (int w = 0; w < 8; w++) s += sr[e][w];
            lg[e] = s;
        }
        float mx = fmaxf(fmaxf(lg[0], lg[1]), fmaxf(lg[2], lg[3]));
        float ex[4], se = 0.f;
#pragma unroll
        for (int e = 0; e < 4; e++) { ex[e] = __expf(lg[e] - mx); se += ex[e]; }
        float inv = 1.f / se;
#pragma unroll
        for (int e = 0; e < 4; e++) g_gate[tok * 4 + e] = ex[e] * inv;
    }
}

// ---------------------------------------------------------------------------
// Kernel 2: QKV projections. Block = (64-token tile, expert e, chunk c).
// Output into q/k/v scratch, layout [B][C][E][H][T][DH]. q pre-scaled.
// ---------------------------------------------------------------------------
__global__ void __launch_bounds__(256) k_qkv(const float* __restrict__ qw) {
    int tile = blockIdx.x, e = blockIdx.y, c = blockIdx.z;
    int tid = threadIdx.x;
    int tx = tid & 15, ty = tid >> 4;

    __shared__ float xs[64][65];
    __shared__ float ws[192][17];

#pragma unroll
    for (int k = 0; k < 16; k++) {
        int idx = tid + k * 256;
        int row = idx >> 6, col = idx & 63;
        xs[row][col] = g_xn[(tile * 64 + row) * Dm + c * DCc + col];
    }

    float acc[4][12];
#pragma unroll
    for (int i = 0; i < 4; i++)
#pragma unroll
        for (int j = 0; j < 12; j++) acc[i][j] = 0.f;

    for (int k0 = 0; k0 < 64; k0 += 16) {
        __syncthreads();
#pragma unroll
        for (int k = 0; k < 12; k++) {
            int idx = tid + k * 256;
            int row = idx >> 4, kk = idx & 15;
            ws[row][kk] = qw[(e * 192 + row) * 64 + k0 + kk];
        }
        __syncthreads();
#pragma unroll
        for (int kk = 0; kk < 16; kk++) {
            float a[4];
#pragma unroll
            for (int i = 0; i < 4; i++) a[i] = xs[ty * 4 + i][k0 + kk];
#pragma unroll
            for (int j = 0; j < 12; j++) {
                float w = ws[tx * 12 + j][kk];
#pragma unroll
                for (int i = 0; i < 4; i++) acc[i][j] += a[i] * w;
            }
        }
    }

    const float qscale = 0.17677669529663689f; // 1/sqrt(32)
#pragma unroll
    for (int i = 0; i < 4; i++) {
        int tkg = tile * 64 + ty * 4 + i;
        int b = tkg >> 10, t = tkg & 1023;
#pragma unroll
        for (int j = 0; j < 12; j++) {
            int row = tx * 12 + j;
            int s   = row >> 6;       // 0=q 1=k 2=v
            int rem = row & 63;
            int h = rem >> 5, dh = rem & 31;
            size_t dst = ((((size_t)(b * Cc + c) * Ee + e) * Hh + h) * Tt + t) * DHh + dh;
            float val = acc[i][j];
            if (s == 0)      g_q[dst] = val * qscale;
            else if (s == 1) g_k[dst] = val;
            else             g_v[dst] = val;
        }
    }
}

// ---------------------------------------------------------------------------
// Kernel 3: flash attention. Block = (group g, 128-query tile), 128 threads.
// One query per thread; K/V tiles (64 keys) staged in smem; broadcast reads.
// ---------------------------------------------------------------------------
__global__ void __launch_bounds__(128) k_attn() {
    int g = blockIdx.y;
    int t = blockIdx.x * 128 + threadIdx.x;

    const float4* qp = (const float4*)(g_q + (size_t)g * Tt * DHh);
    const float4* kp = (const float4*)(g_k + (size_t)g * Tt * DHh);
    const float4* vp = (const float4*)(g_v + (size_t)g * Tt * DHh);

    float4 q[8];
#pragma unroll
    for (int d = 0; d < 8; d++) q[d] = qp[t * 8 + d];

    float4 acc[8];
#pragma unroll
    for (int d = 0; d < 8; d++) acc[d] = make_float4(0.f, 0.f, 0.f, 0.f);
    float m = -1e30f, l = 0.f;

    __shared__ float4 Ks[512];
    __shared__ float4 Vs[512];

    for (int kt = 0; kt < 16; kt++) {
        __syncthreads();
#pragma unroll
        for (int i = 0; i < 4; i++) {
            int r = threadIdx.x + i * 128;
            Ks[r] = kp[kt * 512 + r];
            Vs[r] = vp[kt * 512 + r];
        }
        __syncthreads();
#pragma unroll
        for (int sub = 0; sub < 4; sub++) {
            float sreg[16];
#pragma unroll
            for (int jj = 0; jj < 16; jj++) {
                int j = sub * 16 + jj;
                float s = 0.f;
#pragma unroll
                for (int d = 0; d < 8; d++) {
                    float4 kk = Ks[j * 8 + d];
                    s += q[d].x * kk.x + q[d].y * kk.y + q[d].z * kk.z + q[d].w * kk.w;
                }
                sreg[jj] = s;
            }
            float mt = sreg[0];
#pragma unroll
            for (int jj = 1; jj < 16; jj++) mt = fmaxf(mt, sreg[jj]);
            float mnew = fmaxf(m, mt);
            float corr = __expf(m - mnew);
            l *= corr;
#pragma unroll
            for (int d = 0; d < 8; d++) {
                acc[d].x *= corr; acc[d].y *= corr; acc[d].z *= corr; acc[d].w *= corr;
            }
            m = mnew;
#pragma unroll
            for (int jj = 0; jj < 16; jj++) {
                float p = __expf(sreg[jj] - mnew);
                l += p;
                int j = sub * 16 + jj;
#pragma unroll
                for (int d = 0; d < 8; d++) {
                    float4 vv = Vs[j * 8 + d];
                    acc[d].x += p * vv.x; acc[d].y += p * vv.y;
                    acc[d].z += p * vv.z; acc[d].w += p * vv.w;
                }
            }
        }
    }

    float inv = 1.f / l;
    int bce = g >> 1, h = g & 1;
    float4* yp = (float4*)(g_y + (((size_t)bce * Tt + t) * DCc + h * DHh));
#pragma unroll
    for (int d = 0; d < 8; d++) {
        float4 o = acc[d];
        o.x *= inv; o.y *= inv; o.z *= inv; o.w *= inv;
        yp[d] = o;
    }
}

// ---------------------------------------------------------------------------
// Kernel 4: per-expert output proj + gate-weighted mix. Block = (64-tok, c).
// ---------------------------------------------------------------------------
__global__ void __launch_bounds__(256) k_projgate(const float* __restrict__ pw,
                                                  const float* __restrict__ pb) {
    int tile = blockIdx.x, c = blockIdx.y;
    int tid = threadIdx.x;
    int tx = tid & 15, ty = tid >> 4;

    __shared__ float ysm[64][65];
    __shared__ float wsm[64][65];

    float zacc[4][4];
#pragma unroll
    for (int i = 0; i < 4; i++)
#pragma unroll
        for (int j = 0; j < 4; j++) zacc[i][j] = 0.f;

    for (int e = 0; e < 4; e++) {
        __syncthreads();
#pragma unroll
        for (int k = 0; k < 16; k++) {
            int idx = tid + k * 256;
            int row = idx >> 6, col = idx & 63;
            int tkg = tile * 64 + row;
            int b = tkg >> 10, t = tkg & 1023;
            ysm[row][col] = g_y[(((size_t)(b * Cc + c) * Ee + e) * Tt + t) * DCc + col];
            wsm[row][col] = pw[(e * 64 + row) * 64 + col];
        }
        __syncthreads();
        float part[4][4];
#pragma unroll
        for (int i = 0; i < 4; i++)
#pragma unroll
            for (int j = 0; j < 4; j++) part[i][j] = 0.f;
#pragma unroll 8
        for (int d = 0; d < 64; d++) {
            float a[4], w[4];
#pragma unroll
            for (int i = 0; i < 4; i++) a[i] = ysm[ty * 4 + i][d];
#pragma unroll
            for (int j = 0; j < 4; j++) w[j] = wsm[tx * 4 + j][d];
#pragma unroll
            for (int i = 0; i < 4; i++)
#pragma unroll
                for (int j = 0; j < 4; j++) part[i][j] += a[i] * w[j];
        }
#pragma unroll
        for (int i = 0; i < 4; i++) {
            float gi = g_gate[(tile * 64 + ty * 4 + i) * 4 + e];
#pragma unroll
            for (int j = 0; j < 4; j++)
                zacc[i][j] += gi * (part[i][j] + pb[e * 64 + tx * 4 + j]);
        }
    }
#pragma unroll
    for (int i = 0; i < 4; i++)
#pragma unroll
        for (int j = 0; j < 4; j++)
            g_z[(tile * 64 + ty * 4 + i) * Dm + c * 64 + tx * 4 + j] = zacc[i][j];
}

// ---------------------------------------------------------------------------
// Kernel 5: out = x + z @ out_w^T. Block = (64-tok tile, 64-output quarter).
// ---------------------------------------------------------------------------
__global__ void __launch_bounds__(256) k_final(const float* __restrict__ x,
                                               const float* __restrict__ ow,
                                               float* __restrict__ out) {
    int tile = blockIdx.x, bo = blockIdx.y;
    int tid = threadIdx.x;
    int tx = tid & 15, ty = tid >> 4;

    __shared__ float zsm[64][65];
    __shared__ float wsm[64][65];

    float acc[4][4];
#pragma unroll
    for (int i = 0; i < 4; i++)
#pragma unroll
        for (int j = 0; j < 4; j++) acc[i][j] = 0.f;

    for (int k0 = 0; k0 < 256; k0 += 64) {
        __syncthreads();
#pragma unroll
        for (int k = 0; k < 16; k++) {
            int idx = tid + k * 256;
            int row = idx >> 6, col = idx & 63;
            zsm[row][col] = g_z[(tile * 64 + row) * Dm + k0 + col];
            wsm[row][col] = ow[(bo * 64 + row) * Dm + k0 + col];
        }
        __syncthreads();
#pragma unroll 8
        for (int d = 0; d < 64; d++) {
            float a[4], w[4];
#pragma unroll
            for (int i = 0; i < 4; i++) a[i] = zsm[ty * 4 + i][d];
#pragma unroll
            for (int j = 0; j < 4; j++) w[j] = wsm[tx * 4 + j][d];
#pragma unroll
            for (int i = 0; i < 4; i++)
#pragma unroll
                for (int j = 0; j < 4; j++) acc[i][j] += a[i] * w[j];
        }
    }
#pragma unroll
    for (int i = 0; i < 4; i++) {
        int tok = tile * 64 + ty * 4 + i;
#pragma unroll
        for (int j = 0; j < 4; j++) {
            int o = bo * 64 + tx * 4 + j;
            out[tok * Dm + o] = x[tok * Dm + o] + acc[i][j];
        }
    }
}

// ---------------------------------------------------------------------------
extern "C" void kernel_launch(void* const* d_in, const int* in_sizes, int n_in,
                              void* d_out, int out_size) {
    const float* x   = (const float*)d_in[0];
    const float* nw  = (const float*)d_in[1];
    const float* rw  = (const float*)d_in[2];
    const float* rb  = (const float*)d_in[3];
    const float* qw  = (const float*)d_in[4];
    const float* pw  = (const float*)d_in[5];
    const float* pb  = (const float*)d_in[6];
    const float* ow  = (const float*)d_in[7];
    float* out = (float*)d_out;

    k_ln_router<<<NTOK, 256>>>(x, nw, rw, rb);
    k_qkv<<<dim3(64, Ee, Cc), 256>>>(qw);
    k_attn<<<dim3(Tt / 128, NGRP), 128>>>();
    k_projgate<<<dim3(64, Cc), 256>>>(pw, pb);
    k_final<<<dim3(64, 4), 256>>>(x, ow, out);
}

// round 3
// speedup vs baseline: 3.3942x; 3.3942x over previous
#include <cuda_runtime.h>
#include <cuda_bf16.h>
#include <cstdint>

// Problem constants
#define NTOK 4096   // B*T
#define Dm   256
#define Ee   4
#define Cc   4
#define DCc  64
#define Hh   2
#define DHh  32
#define Tt   1024
#define NGRP 128    // B*C*E*H

// Scratch (device globals; no runtime allocation allowed)
__device__ __align__(16) float g_xn[NTOK * Dm];
__device__ __align__(16) float g_gate[NTOK * Ee];
__device__ __align__(16) __nv_bfloat16 g_qb[NGRP * Tt * DHh];
__device__ __align__(16) __nv_bfloat16 g_kb[NGRP * Tt * DHh];
__device__ __align__(16) __nv_bfloat16 g_vt[NGRP * DHh * Tt];   // transposed: [g][dh][t]
__device__ __align__(16) float g_y[(NGRP / Hh) * Tt * DCc];     // [B,C,E,T,DC]
__device__ __align__(16) float g_z[NTOK * Dm];

// ---------------------------------------------------------------------------
// Kernel 1: LayerNorm + router softmax gate. 1 block per token, 256 threads.
// ---------------------------------------------------------------------------
__global__ void k_ln_router(const float* __restrict__ x,
                            const float* __restrict__ nw,
                            const float* __restrict__ rw,
                            const float* __restrict__ rb) {
    int tok  = blockIdx.x;
    int tid  = threadIdx.x;
    int lane = tid & 31, wid = tid >> 5;

    float v  = x[tok * Dm + tid];
    float s1 = v, s2 = v * v;
#pragma unroll
    for (int o = 16; o; o >>= 1) {
        s1 += __shfl_xor_sync(0xffffffffu, s1, o);
        s2 += __shfl_xor_sync(0xffffffffu, s2, o);
    }
    __shared__ float sh1[8], sh2[8];
    if (lane == 0) { sh1[wid] = s1; sh2[wid] = s2; }
    __syncthreads();
    float a1 = 0.f, a2 = 0.f;
#pragma unroll
    for (int w = 0; w < 8; w++) { a1 += sh1[w]; a2 += sh2[w]; }
    float mean = a1 * (1.f / Dm);
    float var  = a2 * (1.f / Dm) - mean * mean;
    float xnv  = (v - mean) * rsqrtf(var + 1e-5f) * nw[tid];
    g_xn[tok * Dm + tid] = xnv;

    float r0 = xnv * rw[0 * Dm + tid];
    float r1 = xnv * rw[1 * Dm + tid];
    float r2 = xnv * rw[2 * Dm + tid];
    float r3 = xnv * rw[3 * Dm + tid];
#pragma unroll
    for (int o = 16; o; o >>= 1) {
        r0 += __shfl_xor_sync(0xffffffffu, r0, o);
        r1 += __shfl_xor_sync(0xffffffffu, r1, o);
        r2 += __shfl_xor_sync(0xffffffffu, r2, o);
        r3 += __shfl_xor_sync(0xffffffffu, r3, o);
    }
    __shared__ float sr[4][8];
    if (lane == 0) { sr[0][wid] = r0; sr[1][wid] = r1; sr[2][wid] = r2; sr[3][wid] = r3; }
    __syncthreads();
    if (tid == 0) {
        float lg[4];
#pragma unroll
        for (int e = 0; e < 4; e++) {
            float s = rb[e];
#pragma unroll
            for (int w = 0; w < 8; w++) s += sr[e][w];
            lg[e] = s;
        }
        float mx = fmaxf(fmaxf(lg[0], lg[1]), fmaxf(lg[2], lg[3]));
        float ex[4], se = 0.f;
#pragma unroll
        for (int e = 0; e < 4; e++) { ex[e] = __expf(lg[e] - mx); se += ex[e]; }
        float inv = 1.f / se;
#pragma unroll
        for (int e = 0; e < 4; e++) g_gate[tok * 4 + e] = ex[e] * inv;
    }
}

// ---------------------------------------------------------------------------
// Kernel 2: QKV projections (fp32 math, bf16 outputs for the MMA attention).
// Block = (64-token tile, expert e, chunk c). q pre-scaled by 1/sqrt(DH).
// ---------------------------------------------------------------------------
__global__ void __launch_bounds__(256) k_qkv(const float* __restrict__ qw) {
    int tile = blockIdx.x, e = blockIdx.y, c = blockIdx.z;
    int tid = threadIdx.x;
    int tx = tid & 15, ty = tid >> 4;

    __shared__ float xs[64][65];
    __shared__ float ws[192][17];

#pragma unroll
    for (int k = 0; k < 16; k++) {
        int idx = tid + k * 256;
        int row = idx >> 6, col = idx & 63;
        xs[row][col] = g_xn[(tile * 64 + row) * Dm + c * DCc + col];
    }

    float acc[4][12];
#pragma unroll
    for (int i = 0; i < 4; i++)
#pragma unroll
        for (int j = 0; j < 12; j++) acc[i][j] = 0.f;

    for (int k0 = 0; k0 < 64; k0 += 16) {
        __syncthreads();
#pragma unroll
        for (int k = 0; k < 12; k++) {
            int idx = tid + k * 256;
            int row = idx >> 4, kk = idx & 15;
            ws[row][kk] = qw[(e * 192 + row) * 64 + k0 + kk];
        }
        __syncthreads();
#pragma unroll
        for (int kk = 0; kk < 16; kk++) {
            float a[4];
#pragma unroll
            for (int i = 0; i < 4; i++) a[i] = xs[ty * 4 + i][k0 + kk];
#pragma unroll
            for (int j = 0; j < 12; j++) {
                float w = ws[tx * 12 + j][kk];
#pragma unroll
                for (int i = 0; i < 4; i++) acc[i][j] += a[i] * w;
            }
        }
    }

    const float qscale = 0.17677669529663689f; // 1/sqrt(32)
#pragma unroll
    for (int i = 0; i < 4; i++) {
        int tkg = tile * 64 + ty * 4 + i;
        int b = tkg >> 10, t = tkg & 1023;
#pragma unroll
        for (int j = 0; j < 12; j++) {
            int row = tx * 12 + j;
            int s   = row >> 6;       // 0=q 1=k 2=v
            int rem = row & 63;
            int h = rem >> 5, dh = rem & 31;
            size_t gi = (((size_t)(b * Cc + c) * Ee + e) * Hh + h);
            float val = acc[i][j];
            if (s == 0)      g_qb[(gi * Tt + t) * DHh + dh] = __float2bfloat16(val * qscale);
            else if (s == 1) g_kb[(gi * Tt + t) * DHh + dh] = __float2bfloat16(val);
            else             g_vt[(gi * DHh + dh) * Tt + t] = __float2bfloat16(val);
        }
    }
}

// ---------------------------------------------------------------------------
// Kernel 3: flash attention with bf16 mma.sync (m16n8k16), fp32 accumulate.
// Block = 4 warps, 64 query rows. Each warp owns a 16-row m-tile.
// ---------------------------------------------------------------------------
__device__ __forceinline__ void mma16816(float* c, const uint32_t* a,
                                         uint32_t b0, uint32_t b1) {
    asm volatile(
        "mma.sync.aligned.m16n8k16.row.col.f32.bf16.bf16.f32 "
        "{%0,%1,%2,%3}, {%4,%5,%6,%7}, {%8,%9}, {%0,%1,%2,%3};\n"
        : "+f"(c[0]), "+f"(c[1]), "+f"(c[2]), "+f"(c[3])
        : "r"(a[0]), "r"(a[1]), "r"(a[2]), "r"(a[3]), "r"(b0), "r"(b1));
}

__device__ __forceinline__ uint32_t pack2bf(float a, float b) {
    __nv_bfloat162 h = __floats2bfloat162_rn(a, b);
    return *(uint32_t*)&h;
}

__global__ void __launch_bounds__(128) k_attn() {
    int g = blockIdx.y;
    int warp = threadIdx.x >> 5, lane = threadIdx.x & 31;
    int grp = lane >> 2, tid4 = lane & 3;
    int r0 = blockIdx.x * 64 + warp * 16 + grp;

    const __nv_bfloat16* Qg = g_qb + (size_t)g * Tt * DHh;
    const __nv_bfloat16* Kg = g_kb + (size_t)g * Tt * DHh;
    const __nv_bfloat16* Vg = g_vt + (size_t)g * DHh * Tt;

    // Q fragments (m16 x k32): loaded once
    uint32_t qf[2][4];
#pragma unroll
    for (int kc = 0; kc < 2; kc++) {
        qf[kc][0] = *(const uint32_t*)&Qg[(size_t)r0 * DHh + kc * 16 + tid4 * 2];
        qf[kc][1] = *(const uint32_t*)&Qg[(size_t)(r0 + 8) * DHh + kc * 16 + tid4 * 2];
        qf[kc][2] = *(const uint32_t*)&Qg[(size_t)r0 * DHh + kc * 16 + tid4 * 2 + 8];
        qf[kc][3] = *(const uint32_t*)&Qg[(size_t)(r0 + 8) * DHh + kc * 16 + tid4 * 2 + 8];
    }

    __shared__ __nv_bfloat16 Ks[64][40];   // 40-pad: conflict-free frag reads
    __shared__ __nv_bfloat16 VTs[32][72];  // 72-pad: conflict-free frag reads

    float o[4][4];
#pragma unroll
    for (int n = 0; n < 4; n++)
#pragma unroll
        for (int i = 0; i < 4; i++) o[n][i] = 0.f;
    float m0 = -1e30f, m1 = -1e30f, l0 = 0.f, l1 = 0.f;

    for (int kt = 0; kt < 16; kt++) {
        __syncthreads();
#pragma unroll
        for (int i = 0; i < 2; i++) {
            int idx = threadIdx.x + i * 128;
            int row = idx >> 2, seg = idx & 3;
            *(uint4*)&Ks[row][seg * 8] =
                *(const uint4*)&Kg[(size_t)(kt * 64 + row) * DHh + seg * 8];
            int vrow = idx >> 3, vseg = idx & 7;
            *(uint4*)&VTs[vrow][vseg * 8] =
                *(const uint4*)&Vg[(size_t)vrow * Tt + kt * 64 + vseg * 8];
        }
        __syncthreads();

        // S = Q @ K^T for 64 keys: 8 n8-chunks
        float s[8][4];
#pragma unroll
        for (int j = 0; j < 8; j++) {
            s[j][0] = s[j][1] = s[j][2] = s[j][3] = 0.f;
#pragma unroll
            for (int kc = 0; kc < 2; kc++) {
                uint32_t b0 = *(const uint32_t*)&Ks[j * 8 + grp][kc * 16 + tid4 * 2];
                uint32_t b1 = *(const uint32_t*)&Ks[j * 8 + grp][kc * 16 + tid4 * 2 + 8];
                mma16816(s[j], qf[kc], b0, b1);
            }
        }

        // online softmax, rows r0 (c0,c1) and r0+8 (c2,c3)
        float mt0 = -1e30f, mt1 = -1e30f;
#pragma unroll
        for (int j = 0; j < 8; j++) {
            mt0 = fmaxf(mt0, fmaxf(s[j][0], s[j][1]));
            mt1 = fmaxf(mt1, fmaxf(s[j][2], s[j][3]));
        }
        mt0 = fmaxf(mt0, __shfl_xor_sync(0xffffffffu, mt0, 1));
        mt0 = fmaxf(mt0, __shfl_xor_sync(0xffffffffu, mt0, 2));
        mt1 = fmaxf(mt1, __shfl_xor_sync(0xffffffffu, mt1, 1));
        mt1 = fmaxf(mt1, __shfl_xor_sync(0xffffffffu, mt1, 2));
        float mn0 = fmaxf(m0, mt0), mn1 = fmaxf(m1, mt1);
        float cr0 = __expf(m0 - mn0), cr1 = __expf(m1 - mn1);
        float rs0 = 0.f, rs1 = 0.f;
#pragma unroll
        for (int j = 0; j < 8; j++) {
            s[j][0] = __expf(s[j][0] - mn0);
            s[j][1] = __expf(s[j][1] - mn0);
            s[j][2] = __expf(s[j][2] - mn1);
            s[j][3] = __expf(s[j][3] - mn1);
            rs0 += s[j][0] + s[j][1];
            rs1 += s[j][2] + s[j][3];
        }
        rs0 += __shfl_xor_sync(0xffffffffu, rs0, 1);
        rs0 += __shfl_xor_sync(0xffffffffu, rs0, 2);
        rs1 += __shfl_xor_sync(0xffffffffu, rs1, 1);
        rs1 += __shfl_xor_sync(0xffffffffu, rs1, 2);
        l0 = l0 * cr0 + rs0;
        l1 = l1 * cr1 + rs1;
        m0 = mn0; m1 = mn1;
#pragma unroll
        for (int n = 0; n < 4; n++) {
            o[n][0] *= cr0; o[n][1] *= cr0;
            o[n][2] *= cr1; o[n][3] *= cr1;
        }

        // P (bf16 A-frags) directly from S C-frags — no shuffles needed
        uint32_t pf[4][4];
#pragma unroll
        for (int kc = 0; kc < 4; kc++) {
            pf[kc][0] = pack2bf(s[2 * kc][0],     s[2 * kc][1]);
            pf[kc][1] = pack2bf(s[2 * kc][2],     s[2 * kc][3]);
            pf[kc][2] = pack2bf(s[2 * kc + 1][0], s[2 * kc + 1][1]);
            pf[kc][3] = pack2bf(s[2 * kc + 1][2], s[2 * kc + 1][3]);
        }

        // O += P @ V
#pragma unroll
        for (int kc = 0; kc < 4; kc++) {
#pragma unroll
            for (int n = 0; n < 4; n++) {
                uint32_t b0 = *(const uint32_t*)&VTs[n * 8 + grp][kc * 16 + tid4 * 2];
                uint32_t b1 = *(const uint32_t*)&VTs[n * 8 + grp][kc * 16 + tid4 * 2 + 8];
                mma16816(o[n], pf[kc], b0, b1);
            }
        }
    }

    float i0 = 1.f / l0, i1 = 1.f / l1;
    int bce = g >> 1, h = g & 1;
    float* y0 = g_y + ((size_t)bce * Tt + r0) * DCc + h * DHh;
    float* y1 = g_y + ((size_t)bce * Tt + r0 + 8) * DCc + h * DHh;
#pragma unroll
    for (int n = 0; n < 4; n++) {
        *(float2*)&y0[n * 8 + tid4 * 2] = make_float2(o[n][0] * i0, o[n][1] * i0);
        *(float2*)&y1[n * 8 + tid4 * 2] = make_float2(o[n][2] * i1, o[n][3] * i1);
    }
}

// ---------------------------------------------------------------------------
// Kernel 4: per-expert output proj + gate-weighted mix. Block = (64-tok, c).
// ---------------------------------------------------------------------------
__global__ void __launch_bounds__(256) k_projgate(const float* __restrict__ pw,
                                                  const float* __restrict__ pb) {
    int tile = blockIdx.x, c = blockIdx.y;
    int tid = threadIdx.x;
    int tx = tid & 15, ty = tid >> 4;

    __shared__ float ysm[64][65];
    __shared__ float wsm[64][65];

    float zacc[4][4];
#pragma unroll
    for (int i = 0; i < 4; i++)
#pragma unroll
        for (int j = 0; j < 4; j++) zacc[i][j] = 0.f;

    for (int e = 0; e < 4; e++) {
        __syncthreads();
#pragma unroll
        for (int k = 0; k < 16; k++) {
            int idx = tid + k * 256;
            int row = idx >> 6, col = idx & 63;
            int tkg = tile * 64 + row;
            int b = tkg >> 10, t = tkg & 1023;
            ysm[row][col] = g_y[(((size_t)(b * Cc + c) * Ee + e) * Tt + t) * DCc + col];
            wsm[row][col] = pw[(e * 64 + row) * 64 + col];
        }
        __syncthreads();
        float part[4][4];
#pragma unroll
        for (int i = 0; i < 4; i++)
#pragma unroll
            for (int j = 0; j < 4; j++) part[i][j] = 0.f;
#pragma unroll 8
        for (int d = 0; d < 64; d++) {
            float a[4], w[4];
#pragma unroll
            for (int i = 0; i < 4; i++) a[i] = ysm[ty * 4 + i][d];
#pragma unroll
            for (int j = 0; j < 4; j++) w[j] = wsm[tx * 4 + j][d];
#pragma unroll
            for (int i = 0; i < 4; i++)
#pragma unroll
                for (int j = 0; j < 4; j++) part[i][j] += a[i] * w[j];
        }
#pragma unroll
        for (int i = 0; i < 4; i++) {
            float gi = g_gate[(tile * 64 + ty * 4 + i) * 4 + e];
#pragma unroll
            for (int j = 0; j < 4; j++)
                zacc[i][j] += gi * (part[i][j] + pb[e * 64 + tx * 4 + j]);
        }
    }
#pragma unroll
    for (int i = 0; i < 4; i++)
#pragma unroll
        for (int j = 0; j < 4; j++)
            g_z[(tile * 64 + ty * 4 + i) * Dm + c * 64 + tx * 4 + j] = zacc[i][j];
}

// ---------------------------------------------------------------------------
// Kernel 5: out = x + z @ out_w^T. Block = (64-tok tile, 64-output quarter).
// ---------------------------------------------------------------------------
__global__ void __launch_bounds__(256) k_final(const float* __restrict__ x,
                                               const float* __restrict__ ow,
                                               float* __restrict__ out) {
    int tile = blockIdx.x, bo = blockIdx.y;
    int tid = threadIdx.x;
    int tx = tid & 15, ty = tid >> 4;

    __shared__ float zsm[64][65];
    __shared__ float wsm[64][65];

    float acc[4][4];
#pragma unroll
    for (int i = 0; i < 4; i++)
#pragma unroll
        for (int j = 0; j < 4; j++) acc[i][j] = 0.f;

    for (int k0 = 0; k0 < 256; k0 += 64) {
        __syncthreads();
#pragma unroll
        for (int k = 0; k < 16; k++) {
            int idx = tid + k * 256;
            int row = idx >> 6, col = idx & 63;
            zsm[row][col] = g_z[(tile * 64 + row) * Dm + k0 + col];
            wsm[row][col] = ow[(bo * 64 + row) * Dm + k0 + col];
        }
        __syncthreads();
#pragma unroll 8
        for (int d = 0; d < 64; d++) {
            float a[4], w[4];
#pragma unroll
            for (int i = 0; i < 4; i++) a[i] = zsm[ty * 4 + i][d];
#pragma unroll
            for (int j = 0; j < 4; j++) w[j] = wsm[tx * 4 + j][d];
#pragma unroll
            for (int i = 0; i < 4; i++)
#pragma unroll
                for (int j = 0; j < 4; j++) acc[i][j] += a[i] * w[j];
        }
    }
#pragma unroll
    for (int i = 0; i < 4; i++) {
        int tok = tile * 64 + ty * 4 + i;
#pragma unroll
        for (int j = 0; j < 4; j++) {
            int o = bo * 64 + tx * 4 + j;
            out[tok * Dm + o] = x[tok * Dm + o] + acc[i][j];
        }
    }
}

// ---------------------------------------------------------------------------
extern "C" void kernel_launch(void* const* d_in, const int* in_sizes, int n_in,
                              void* d_out, int out_size) {
    const float* x   = (const float*)d_in[0];
    const float* nw  = (const float*)d_in[1];
    const float* rw  = (const float*)d_in[2];
    const float* rb  = (const float*)d_in[3];
    const float* qw  = (const float*)d_in[4];
    const float* pw  = (const float*)d_in[5];
    const float* pb  = (const float*)d_in[6];
    const float* ow  = (const float*)d_in[7];
    float* out = (float*)d_out;

    k_ln_router<<<NTOK, 256>>>(x, nw, rw, rb);
    k_qkv<<<dim3(64, Ee, Cc), 256>>>(qw);
    k_attn<<<dim3(Tt / 64, NGRP), 128>>>();
    k_projgate<<<dim3(64, Cc), 256>>>(pw, pb);
    k_final<<<dim3(64, 4), 256>>>(x, ow, out);
}

// round 5
// speedup vs baseline: 6.5856x; 1.9403x over previous
#include <cuda_runtime.h>
#include <cuda_bf16.h>
#include <cstdint>

// Problem constants
#define NTOK 4096   // B*T
#define Dm   256
#define Ee   4
#define Cc   4
#define DCc  64
#define Hh   2
#define DHh  32
#define Tt   1024
#define NGRP 128    // B*C*E*H

// Scratch (device globals)
__device__ __align__(16) __nv_bfloat16 g_xnb[NTOK * Dm];
__device__ __align__(16) float g_gate[NTOK * Ee];
__device__ __align__(16) __nv_bfloat16 g_qb[NGRP * Tt * DHh];
__device__ __align__(16) __nv_bfloat16 g_kb[NGRP * Tt * DHh];
__device__ __align__(16) __nv_bfloat16 g_vt[NGRP * DHh * Tt];     // [g][dh][t]
__device__ __align__(16) __nv_bfloat16 g_yb[(NGRP / Hh) * Tt * DCc]; // [B,C,E,T,DC]
__device__ __align__(16) __nv_bfloat16 g_zb[NTOK * Dm];
// bf16 weight copies
__device__ __align__(16) __nv_bfloat16 g_qwb[Ee * 192 * 64];
__device__ __align__(16) __nv_bfloat16 g_pwb[Ee * 64 * 64];
__device__ __align__(16) __nv_bfloat16 g_owb[Dm * Dm];

__device__ __forceinline__ void mma16816(float* c, const uint32_t* a,
                                         uint32_t b0, uint32_t b1) {
    asm volatile(
        "mma.sync.aligned.m16n8k16.row.col.f32.bf16.bf16.f32 "
        "{%0,%1,%2,%3}, {%4,%5,%6,%7}, {%8,%9}, {%0,%1,%2,%3};\n"
        : "+f"(c[0]), "+f"(c[1]), "+f"(c[2]), "+f"(c[3])
        : "r"(a[0]), "r"(a[1]), "r"(a[2]), "r"(a[3]), "r"(b0), "r"(b1));
}

__device__ __forceinline__ uint32_t pack2bf(float a, float b) {
    __nv_bfloat162 h = __floats2bfloat162_rn(a, b);
    return *(uint32_t*)&h;
}

// ---------------------------------------------------------------------------
// Kernel 0: convert weights to bf16 (tiny, runs every launch; deterministic)
// ---------------------------------------------------------------------------
__global__ void k_prep(const float* __restrict__ qw,
                       const float* __restrict__ pw,
                       const float* __restrict__ ow) {
    int i = blockIdx.x * 256 + threadIdx.x;           // 0 .. 65535
    g_owb[i] = __float2bfloat16(ow[i]);
    if (i < Ee * 192 * 64) g_qwb[i] = __float2bfloat16(qw[i]);
    if (i < Ee * 64 * 64)  g_pwb[i] = __float2bfloat16(pw[i]);
}

// ---------------------------------------------------------------------------
// Kernel 1: LayerNorm + router softmax gate. 1 block per token, 256 threads.
// ---------------------------------------------------------------------------
__global__ void k_ln_router(const float* __restrict__ x,
                            const float* __restrict__ nw,
                            const float* __restrict__ rw,
                            const float* __restrict__ rb) {
    int tok  = blockIdx.x;
    int tid  = threadIdx.x;
    int lane = tid & 31, wid = tid >> 5;

    float v  = x[tok * Dm + tid];
    float s1 = v, s2 = v * v;
#pragma unroll
    for (int o = 16; o; o >>= 1) {
        s1 += __shfl_xor_sync(0xffffffffu, s1, o);
        s2 += __shfl_xor_sync(0xffffffffu, s2, o);
    }
    __shared__ float sh1[8], sh2[8];
    if (lane == 0) { sh1[wid] = s1; sh2[wid] = s2; }
    __syncthreads();
    float a1 = 0.f, a2 = 0.f;
#pragma unroll
    for (int w = 0; w < 8; w++) { a1 += sh1[w]; a2 += sh2[w]; }
    float mean = a1 * (1.f / Dm);
    float var  = a2 * (1.f / Dm) - mean * mean;
    float xnv  = (v - mean) * rsqrtf(var + 1e-5f) * nw[tid];
    g_xnb[tok * Dm + tid] = __float2bfloat16(xnv);

    float r0 = xnv * rw[0 * Dm + tid];
    float r1 = xnv * rw[1 * Dm + tid];
    float r2 = xnv * rw[2 * Dm + tid];
    float r3 = xnv * rw[3 * Dm + tid];
#pragma unroll
    for (int o = 16; o; o >>= 1) {
        r0 += __shfl_xor_sync(0xffffffffu, r0, o);
        r1 += __shfl_xor_sync(0xffffffffu, r1, o);
        r2 += __shfl_xor_sync(0xffffffffu, r2, o);
        r3 += __shfl_xor_sync(0xffffffffu, r3, o);
    }
    __shared__ float sr[4][8];
    if (lane == 0) { sr[0][wid] = r0; sr[1][wid] = r1; sr[2][wid] = r2; sr[3][wid] = r3; }
    __syncthreads();
    if (tid == 0) {
        float lg[4];
#pragma unroll
        for (int e = 0; e < 4; e++) {
            float s = rb[e];
#pragma unroll
            for (int w = 0; w < 8; w++) s += sr[e][w];
            lg[e] = s;
        }
        float mx = fmaxf(fmaxf(lg[0], lg[1]), fmaxf(lg[2], lg[3]));
        float ex[4], se = 0.f;
#pragma unroll
        for (int e = 0; e < 4; e++) { ex[e] = __expf(lg[e] - mx); se += ex[e]; }
        float inv = 1.f / se;
#pragma unroll
        for (int e = 0; e < 4; e++) g_gate[tok * 4 + e] = ex[e] * inv;
    }
}

// ---------------------------------------------------------------------------
// Kernel 2: QKV projection via bf16 MMA. Block = (64-tok tile, e, c).
// M=64, N=192, K=64. 8 warps: 4 m-tiles x 2 n-halves (96 each).
// ---------------------------------------------------------------------------
__global__ void __launch_bounds__(256) k_qkv(int dummy) {
    int tile = blockIdx.x, e = blockIdx.y, c = blockIdx.z;
    int tid = threadIdx.x;
    int warp = tid >> 5, lane = tid & 31;
    int grp = lane >> 2, tid4 = lane & 3;
    int wm = warp >> 1, wn = warp & 1;
    int m0 = wm * 16, n0 = wn * 96;

    __shared__ __nv_bfloat16 xs[64][72];
    __shared__ __nv_bfloat16 ws[192][72];

#pragma unroll
    for (int i = 0; i < 2; i++) {
        int idx = tid + i * 256;
        int row = idx >> 3, seg = idx & 7;
        *(uint4*)&xs[row][seg * 8] =
            *(const uint4*)&g_xnb[(tile * 64 + row) * Dm + c * 64 + seg * 8];
    }
#pragma unroll
    for (int i = 0; i < 6; i++) {
        int idx = tid + i * 256;
        int row = idx >> 3, seg = idx & 7;
        *(uint4*)&ws[row][seg * 8] =
            *(const uint4*)&g_qwb[(e * 192 + row) * 64 + seg * 8];
    }
    __syncthreads();

    float acc[12][4];
#pragma unroll
    for (int j = 0; j < 12; j++)
#pragma unroll
        for (int i = 0; i < 4; i++) acc[j][i] = 0.f;

#pragma unroll
    for (int k0 = 0; k0 < 64; k0 += 16) {
        uint32_t a[4];
        a[0] = *(const uint32_t*)&xs[m0 + grp][k0 + tid4 * 2];
        a[1] = *(const uint32_t*)&xs[m0 + grp + 8][k0 + tid4 * 2];
        a[2] = *(const uint32_t*)&xs[m0 + grp][k0 + tid4 * 2 + 8];
        a[3] = *(const uint32_t*)&xs[m0 + grp + 8][k0 + tid4 * 2 + 8];
#pragma unroll
        for (int j = 0; j < 12; j++) {
            uint32_t b0 = *(const uint32_t*)&ws[n0 + j * 8 + grp][k0 + tid4 * 2];
            uint32_t b1 = *(const uint32_t*)&ws[n0 + j * 8 + grp][k0 + tid4 * 2 + 8];
            mma16816(acc[j], a, b0, b1);
        }
    }

    const float qscale = 0.17677669529663689f; // 1/sqrt(32)
    int t_lo = tile * 64 + m0 + grp;
    int b = t_lo >> 10;
    int tt_lo = t_lo & 1023, tt_hi = tt_lo + 8;
#pragma unroll
    for (int j = 0; j < 12; j++) {
        int n = n0 + j * 8 + tid4 * 2;
        int s = n >> 6, rem = n & 63;
        int h = rem >> 5, dh = rem & 31;
        size_t gi = ((size_t)(b * Cc + c) * Ee + e) * Hh + h;
        if (s == 0) {
            *(uint32_t*)&g_qb[(gi * Tt + tt_lo) * DHh + dh] =
                pack2bf(acc[j][0] * qscale, acc[j][1] * qscale);
            *(uint32_t*)&g_qb[(gi * Tt + tt_hi) * DHh + dh] =
                pack2bf(acc[j][2] * qscale, acc[j][3] * qscale);
        } else if (s == 1) {
            *(uint32_t*)&g_kb[(gi * Tt + tt_lo) * DHh + dh] = pack2bf(acc[j][0], acc[j][1]);
            *(uint32_t*)&g_kb[(gi * Tt + tt_hi) * DHh + dh] = pack2bf(acc[j][2], acc[j][3]);
        } else {
            g_vt[(gi * DHh + dh) * Tt + tt_lo]     = __float2bfloat16(acc[j][0]);
            g_vt[(gi * DHh + dh + 1) * Tt + tt_lo] = __float2bfloat16(acc[j][1]);
            g_vt[(gi * DHh + dh) * Tt + tt_hi]     = __float2bfloat16(acc[j][2]);
            g_vt[(gi * DHh + dh + 1) * Tt + tt_hi] = __float2bfloat16(acc[j][3]);
        }
    }
}

// ---------------------------------------------------------------------------
// Kernel 3: flash attention, bf16 mma.sync, fp32 accumulate.
// ---------------------------------------------------------------------------
__global__ void __launch_bounds__(128) k_attn() {
    int g = blockIdx.y;
    int warp = threadIdx.x >> 5, lane = threadIdx.x & 31;
    int grp = lane >> 2, tid4 = lane & 3;
    int r0 = blockIdx.x * 64 + warp * 16 + grp;

    const __nv_bfloat16* Qg = g_qb + (size_t)g * Tt * DHh;
    const __nv_bfloat16* Kg = g_kb + (size_t)g * Tt * DHh;
    const __nv_bfloat16* Vg = g_vt + (size_t)g * DHh * Tt;

    uint32_t qf[2][4];
#pragma unroll
    for (int kc = 0; kc < 2; kc++) {
        qf[kc][0] = *(const uint32_t*)&Qg[(size_t)r0 * DHh + kc * 16 + tid4 * 2];
        qf[kc][1] = *(const uint32_t*)&Qg[(size_t)(r0 + 8) * DHh + kc * 16 + tid4 * 2];
        qf[kc][2] = *(const uint32_t*)&Qg[(size_t)r0 * DHh + kc * 16 + tid4 * 2 + 8];
        qf[kc][3] = *(const uint32_t*)&Qg[(size_t)(r0 + 8) * DHh + kc * 16 + tid4 * 2 + 8];
    }

    __shared__ __nv_bfloat16 Ks[64][40];
    __shared__ __nv_bfloat16 VTs[32][72];

    float o[4][4];
#pragma unroll
    for (int n = 0; n < 4; n++)
#pragma unroll
        for (int i = 0; i < 4; i++) o[n][i] = 0.f;
    float m0 = -1e30f, m1 = -1e30f, l0 = 0.f, l1 = 0.f;

    for (int kt = 0; kt < 16; kt++) {
        __syncthreads();
#pragma unroll
        for (int i = 0; i < 2; i++) {
            int idx = threadIdx.x + i * 128;
            int row = idx >> 2, seg = idx & 3;
            *(uint4*)&Ks[row][seg * 8] =
                *(const uint4*)&Kg[(size_t)(kt * 64 + row) * DHh + seg * 8];
            int vrow = idx >> 3, vseg = idx & 7;
            *(uint4*)&VTs[vrow][vseg * 8] =
                *(const uint4*)&Vg[(size_t)vrow * Tt + kt * 64 + vseg * 8];
        }
        __syncthreads();

        float s[8][4];
#pragma unroll
        for (int j = 0; j < 8; j++) {
            s[j][0] = s[j][1] = s[j][2] = s[j][3] = 0.f;
#pragma unroll
            for (int kc = 0; kc < 2; kc++) {
                uint32_t b0 = *(const uint32_t*)&Ks[j * 8 + grp][kc * 16 + tid4 * 2];
                uint32_t b1 = *(const uint32_t*)&Ks[j * 8 + grp][kc * 16 + tid4 * 2 + 8];
                mma16816(s[j], qf[kc], b0, b1);
            }
        }

        float mt0 = -1e30f, mt1 = -1e30f;
#pragma unroll
        for (int j = 0; j < 8; j++) {
            mt0 = fmaxf(mt0, fmaxf(s[j][0], s[j][1]));
            mt1 = fmaxf(mt1, fmaxf(s[j][2], s[j][3]));
        }
        mt0 = fmaxf(mt0, __shfl_xor_sync(0xffffffffu, mt0, 1));
        mt0 = fmaxf(mt0, __shfl_xor_sync(0xffffffffu, mt0, 2));
        mt1 = fmaxf(mt1, __shfl_xor_sync(0xffffffffu, mt1, 1));
        mt1 = fmaxf(mt1, __shfl_xor_sync(0xffffffffu, mt1, 2));
        float mn0 = fmaxf(m0, mt0), mn1 = fmaxf(m1, mt1);
        float cr0 = __expf(m0 - mn0), cr1 = __expf(m1 - mn1);
        float rs0 = 0.f, rs1 = 0.f;
#pragma unroll
        for (int j = 0; j < 8; j++) {
            s[j][0] = __expf(s[j][0] - mn0);
            s[j][1] = __expf(s[j][1] - mn0);
            s[j][2] = __expf(s[j][2] - mn1);
            s[j][3] = __expf(s[j][3] - mn1);
            rs0 += s[j][0] + s[j][1];
            rs1 += s[j][2] + s[j][3];
        }
        rs0 += __shfl_xor_sync(0xffffffffu, rs0, 1);
        rs0 += __shfl_xor_sync(0xffffffffu, rs0, 2);
        rs1 += __shfl_xor_sync(0xffffffffu, rs1, 1);
        rs1 += __shfl_xor_sync(0xffffffffu, rs1, 2);
        l0 = l0 * cr0 + rs0;
        l1 = l1 * cr1 + rs1;
        m0 = mn0; m1 = mn1;
#pragma unroll
        for (int n = 0; n < 4; n++) {
            o[n][0] *= cr0; o[n][1] *= cr0;
            o[n][2] *= cr1; o[n][3] *= cr1;
        }

        uint32_t pf[4][4];
#pragma unroll
        for (int kc = 0; kc < 4; kc++) {
            pf[kc][0] = pack2bf(s[2 * kc][0],     s[2 * kc][1]);
            pf[kc][1] = pack2bf(s[2 * kc][2],     s[2 * kc][3]);
            pf[kc][2] = pack2bf(s[2 * kc + 1][0], s[2 * kc + 1][1]);
            pf[kc][3] = pack2bf(s[2 * kc + 1][2], s[2 * kc + 1][3]);
        }

#pragma unroll
        for (int kc = 0; kc < 4; kc++) {
#pragma unroll
            for (int n = 0; n < 4; n++) {
                uint32_t b0 = *(const uint32_t*)&VTs[n * 8 + grp][kc * 16 + tid4 * 2];
                uint32_t b1 = *(const uint32_t*)&VTs[n * 8 + grp][kc * 16 + tid4 * 2 + 8];
                mma16816(o[n], pf[kc], b0, b1);
            }
        }
    }

    float i0 = 1.f / l0, i1 = 1.f / l1;
    int bce = g >> 1, h = g & 1;
    __nv_bfloat16* y0 = g_yb + ((size_t)bce * Tt + r0) * DCc + h * DHh;
    __nv_bfloat16* y1 = g_yb + ((size_t)bce * Tt + r0 + 8) * DCc + h * DHh;
#pragma unroll
    for (int n = 0; n < 4; n++) {
        *(uint32_t*)&y0[n * 8 + tid4 * 2] = pack2bf(o[n][0] * i0, o[n][1] * i0);
        *(uint32_t*)&y1[n * 8 + tid4 * 2] = pack2bf(o[n][2] * i1, o[n][3] * i1);
    }
}

// ---------------------------------------------------------------------------
// Kernel 4: per-expert proj + gate mix via bf16 MMA. Block = (64-tok, c).
// 8 warps: 4 m-tiles x 2 n-halves (32 each). Loops over 4 experts.
// ---------------------------------------------------------------------------
__global__ void __launch_bounds__(256) k_projgate(const float* __restrict__ pb) {
    int tile = blockIdx.x, c = blockIdx.y;
    int tid = threadIdx.x;
    int warp = tid >> 5, lane = tid & 31;
    int grp = lane >> 2, tid4 = lane & 3;
    int wm = warp >> 1, wn = warp & 1;
    int m0 = wm * 16, n0 = wn * 32;

    int bq = tile >> 4;                // batch
    int t0 = (tile & 15) * 64;         // token offset within batch

    __shared__ __nv_bfloat16 ys[64][72];
    __shared__ __nv_bfloat16 ws[64][72];

    int t_lo = tile * 64 + m0 + grp;
    int t_hi = t_lo + 8;

    float zacc[4][4];
#pragma unroll
    for (int j = 0; j < 4; j++)
#pragma unroll
        for (int i = 0; i < 4; i++) zacc[j][i] = 0.f;

    for (int e = 0; e < 4; e++) {
        __syncthreads();
#pragma unroll
        for (int i = 0; i < 2; i++) {
            int idx = tid + i * 256;
            int row = idx >> 3, seg = idx & 7;
            *(uint4*)&ys[row][seg * 8] =
                *(const uint4*)&g_yb[(((size_t)(bq * Cc + c) * Ee + e) * Tt + t0 + row) * DCc + seg * 8];
            *(uint4*)&ws[row][seg * 8] =
                *(const uint4*)&g_pwb[(e * 64 + row) * 64 + seg * 8];
        }
        __syncthreads();

        float part[4][4];
#pragma unroll
        for (int j = 0; j < 4; j++)
            part[j][0] = part[j][1] = part[j][2] = part[j][3] = 0.f;
#pragma unroll
        for (int k0 = 0; k0 < 64; k0 += 16) {
            uint32_t a[4];
            a[0] = *(const uint32_t*)&ys[m0 + grp][k0 + tid4 * 2];
            a[1] = *(const uint32_t*)&ys[m0 + grp + 8][k0 + tid4 * 2];
            a[2] = *(const uint32_t*)&ys[m0 + grp][k0 + tid4 * 2 + 8];
            a[3] = *(const uint32_t*)&ys[m0 + grp + 8][k0 + tid4 * 2 + 8];
#pragma unroll
            for (int j = 0; j < 4; j++) {
                uint32_t b0 = *(const uint32_t*)&ws[n0 + j * 8 + grp][k0 + tid4 * 2];
                uint32_t b1 = *(const uint32_t*)&ws[n0 + j * 8 + grp][k0 + tid4 * 2 + 8];
                mma16816(part[j], a, b0, b1);
            }
        }

        float g0 = g_gate[t_lo * 4 + e];
        float g1 = g_gate[t_hi * 4 + e];
#pragma unroll
        for (int j = 0; j < 4; j++) {
            int n = n0 + j * 8 + tid4 * 2;
            float pb0 = pb[e * 64 + n], pb1 = pb[e * 64 + n + 1];
            zacc[j][0] += g0 * (part[j][0] + pb0);
            zacc[j][1] += g0 * (part[j][1] + pb1);
            zacc[j][2] += g1 * (part[j][2] + pb0);
            zacc[j][3] += g1 * (part[j][3] + pb1);
        }
    }

#pragma unroll
    for (int j = 0; j < 4; j++) {
        int n = c * 64 + n0 + j * 8 + tid4 * 2;
        *(uint32_t*)&g_zb[t_lo * Dm + n] = pack2bf(zacc[j][0], zacc[j][1]);
        *(uint32_t*)&g_zb[t_hi * Dm + n] = pack2bf(zacc[j][2], zacc[j][3]);
    }
}

// ---------------------------------------------------------------------------
// Kernel 5: out = x + z @ out_w^T via bf16 MMA. Block = (64-tok, 128-col).
// 8 warps: 4 m-tiles x 2 n-halves (64 each). K=256 in 4 stages of 64.
// ---------------------------------------------------------------------------
__global__ void __launch_bounds__(256) k_final(const float* __restrict__ x,
                                               float* __restrict__ out) {
    int tile = blockIdx.x, nb = blockIdx.y;
    int tid = threadIdx.x;
    int warp = tid >> 5, lane = tid & 31;
    int grp = lane >> 2, tid4 = lane & 3;
    int wm = warp >> 1, wn = warp & 1;
    int m0 = wm * 16, n0 = wn * 64;

    __shared__ __nv_bfloat16 zs[64][72];
    __shared__ __nv_bfloat16 ws[128][72];

    float acc[8][4];
#pragma unroll
    for (int j = 0; j < 8; j++)
        acc[j][0] = acc[j][1] = acc[j][2] = acc[j][3] = 0.f;

    for (int kb = 0; kb < 4; kb++) {
        __syncthreads();
#pragma unroll
        for (int i = 0; i < 2; i++) {
            int idx = tid + i * 256;
            int row = idx >> 3, seg = idx & 7;
            *(uint4*)&zs[row][seg * 8] =
                *(const uint4*)&g_zb[(tile * 64 + row) * Dm + kb * 64 + seg * 8];
        }
#pragma unroll
        for (int i = 0; i < 4; i++) {
            int idx = tid + i * 256;
            int row = idx >> 3, seg = idx & 7;
            *(uint4*)&ws[row][seg * 8] =
                *(const uint4*)&g_owb[(nb * 128 + row) * Dm + kb * 64 + seg * 8];
        }
        __syncthreads();

#pragma unroll
        for (int k0 = 0; k0 < 64; k0 += 16) {
            uint32_t a[4];
            a[0] = *(const uint32_t*)&zs[m0 + grp][k0 + tid4 * 2];
            a[1] = *(const uint32_t*)&zs[m0 + grp + 8][k0 + tid4 * 2];
            a[2] = *(const uint32_t*)&zs[m0 + grp][k0 + tid4 * 2 + 8];
            a[3] = *(const uint32_t*)&zs[m0 + grp + 8][k0 + tid4 * 2 + 8];
#pragma unroll
            for (int j = 0; j < 8; j++) {
                uint32_t b0 = *(const uint32_t*)&ws[n0 + j * 8 + grp][k0 + tid4 * 2];
                uint32_t b1 = *(const uint32_t*)&ws[n0 + j * 8 + grp][k0 + tid4 * 2 + 8];
                mma16816(acc[j], a, b0, b1);
            }
        }
    }

    int t_lo = tile * 64 + m0 + grp;
    int t_hi = t_lo + 8;
#pragma unroll
    for (int j = 0; j < 8; j++) {
        int n = nb * 128 + n0 + j * 8 + tid4 * 2;
        float2 x0 = *(const float2*)&x[t_lo * Dm + n];
        float2 x1 = *(const float2*)&x[t_hi * Dm + n];
        *(float2*)&out[t_lo * Dm + n] = make_float2(x0.x + acc[j][0], x0.y + acc[j][1]);
        *(float2*)&out[t_hi * Dm + n] = make_float2(x1.x + acc[j][2], x1.y + acc[j][3]);
    }
}

// ---------------------------------------------------------------------------
extern "C" void kernel_launch(void* const* d_in, const int* in_sizes, int n_in,
                              void* d_out, int out_size) {
    const float* x   = (const float*)d_in[0];
    const float* nw  = (const float*)d_in[1];
    const float* rw  = (const float*)d_in[2];
    const float* rb  = (const float*)d_in[3];
    const float* qw  = (const float*)d_in[4];
    const float* pw  = (const float*)d_in[5];
    const float* pb  = (const float*)d_in[6];
    const float* ow  = (const float*)d_in[7];
    float* out = (float*)d_out;

    k_prep<<<256, 256>>>(qw, pw, ow);
    k_ln_router<<<NTOK, 256>>>(x, nw, rw, rb);
    k_qkv<<<dim3(64, Ee, Cc), 256>>>(0);
    k_attn<<<dim3(Tt / 64, NGRP), 128>>>();
    k_projgate<<<dim3(64, Cc), 256>>>(pb);
    k_final<<<dim3(64, 2), 256>>>(x, out);
}